// round 16
// baseline (speedup 1.0000x reference)
#include <cuda_runtime.h>
#include <cstdint>

#define NROI 6144
#define NCLS 20
#define KSEL 615            // ceil(0.1 * 6144)
#define CSORT 1024
#define IOU_TH 0.25f
#define LMAX 16384
#define GMAX 2560
#define NFB 48              // final blocks (128 ROIs each)
#define KCAP 128            // staged kept-list capacity per class

// ---- scratch (device globals; no allocations allowed) ----
__device__ float g_predsT[NCLS * NROI];
__device__ int g_list[LMAX];
__device__ unsigned long long g_lv[LMAX];    // packed (prob_bits<<32)|(NCLS-c)
__device__ int g_cnt;                        // reset by final kernel for replay

__device__ __forceinline__ void upd(float& mv, int& mj, float v, int j) {
    if (v > mv || (v == mv && j < mj)) { mv = v; mj = j; }
}

__device__ __forceinline__ unsigned long long
blockMinU64(unsigned long long v, unsigned long long* s_red, int t) {
    #pragma unroll
    for (int o = 16; o; o >>= 1) {
        unsigned long long u = __shfl_xor_sync(0xFFFFFFFFu, v, o);
        v = (u < v) ? u : v;
    }
    if ((t & 31) == 0) s_red[t >> 5] = v;
    __syncthreads();
    if (t < 32) {
        unsigned long long w = s_red[t];
        #pragma unroll
        for (int o = 16; o; o >>= 1) {
            unsigned long long u = __shfl_xor_sync(0xFFFFFFFFu, w, o);
            w = (u < w) ? u : w;
        }
        if (t == 0) s_red[0] = w;
    }
    __syncthreads();
    unsigned long long r = s_red[0];
    __syncthreads();
    return r;
}

// ============================================================
// Kernel 0: coalesced float4 transpose; skip label-0 columns.
// NO explicit PDL trigger: completion event fires at grid exit,
// guaranteeing g_predsT visibility to the dependent kernel.
// ============================================================
__global__ void __launch_bounds__(256)
preds_kernel(const float4* __restrict__ pc4, const float4* __restrict__ pd4,
             const int* __restrict__ labels) {
    __shared__ float sp[64 * 21];
    __shared__ int s_lab[NCLS];
    const int b  = blockIdx.x;
    const int t  = threadIdx.x;
    const int i0 = b * 64;
    const int base4 = b * 336;

    if (t < NCLS) s_lab[t] = labels[t];

    float4* sp4 = (float4*)sp;
    #pragma unroll
    for (int r = 0; r < 2; ++r) {
        int idx = t + r * 256;
        if (idx < 336) {
            float4 a = pc4[base4 + idx];
            float4 d = pd4[base4 + idx];
            float4 o;
            o.x = a.x * d.x; o.y = a.y * d.y; o.z = a.z * d.z; o.w = a.w * d.w;
            sp4[idx] = o;
        }
    }
    __syncthreads();
    #pragma unroll
    for (int r = 0; r < 5; ++r) {
        int e = t + r * 256;
        int c = e >> 6;
        int i = e & 63;
        if (s_lab[c])
            g_predsT[c * NROI + i0 + i] = sp[i * 21 + c + 1];
    }
}

// ============================================================
// Kernel 1: one block per class (PDL-dependent on preds).
// NO explicit trigger (kept-list visibility for the final kernel).
// ============================================================
__global__ void __launch_bounds__(1024, 1)
class_nms_kernel(const int* __restrict__ labels,
                 const float* __restrict__ iou) {
    __shared__ unsigned long long cand[CSORT];
    __shared__ unsigned long long s_red[32];
    __shared__ unsigned int sh_hist[256];
    __shared__ unsigned int sh_wsum[8];
    __shared__ unsigned int sh_prefix, sh_k;
    __shared__ int sh_nc, sh_kc, sh_base;
    __shared__ int s_kidx[KCAP];
    __shared__ unsigned long long s_klv[KCAP];

    const int c = blockIdx.x;
    const int t = threadIdx.x;

    const int lab = labels[c];                          // input array: race-free
    cudaGridDependencySynchronize();                    // wait for preds grid

    if (lab == 0) return;

    unsigned int key[6];
    #pragma unroll
    for (int r = 0; r < 6; ++r)
        key[r] = ~__float_as_uint(g_predsT[c * NROI + r * 1024 + t]);
    if (t == 0) { sh_prefix = 0; sh_k = KSEL; }
    __syncthreads();

    // ---- 4-pass MSB radix select (exact threshold) ----
    for (int shift = 24; shift >= 0; shift -= 8) {
        if (t < 256) sh_hist[t] = 0;
        __syncthreads();
        const unsigned int prefix = sh_prefix;
        const unsigned int kcur   = sh_k;
        const unsigned int pmask  = (shift == 24) ? 0u : (0xFFFFFFFFu << (shift + 8));
        #pragma unroll
        for (int r = 0; r < 6; ++r) {
            bool active = ((key[r] & pmask) == prefix);
            unsigned int act = __ballot_sync(0xFFFFFFFFu, active);
            if (active) {
                unsigned int bin = (key[r] >> shift) & 0xFF;
                unsigned int peers = __match_any_sync(act, bin);
                if ((t & 31) == __ffs(peers) - 1)
                    atomicAdd(&sh_hist[bin], (unsigned int)__popc(peers));
            }
        }
        __syncthreads();
        unsigned int x = 0, hval = 0;
        if (t < 256) {
            hval = sh_hist[t];
            x = hval;
            #pragma unroll
            for (int off = 1; off < 32; off <<= 1) {
                unsigned int y = __shfl_up_sync(0xFFFFFFFFu, x, off);
                if ((t & 31) >= off) x += y;
            }
            if ((t & 31) == 31) sh_wsum[t >> 5] = x;
        }
        __syncthreads();
        if (t < 8) {
            unsigned int w = sh_wsum[t];
            #pragma unroll
            for (int off = 1; off < 8; off <<= 1) {
                unsigned int y = __shfl_up_sync(0xFFu, w, off);
                if (t >= off) w += y;
            }
            sh_wsum[t] = w;
        }
        __syncthreads();
        if (t < 256) {
            unsigned int incl = x + ((t >= 32) ? sh_wsum[(t >> 5) - 1] : 0u);
            unsigned int excl = incl - hval;
            if (incl >= kcur && excl < kcur) {
                sh_prefix = prefix | ((unsigned int)t << shift);
                sh_k = kcur - excl;
            }
        }
        __syncthreads();
    }
    const unsigned int thr = sh_prefix;
    const int m = (int)sh_k;

    // ---- warp-aggregated compaction (key <= thr), unsorted ----
    if (t == 0) sh_nc = 0;
    __syncthreads();
    #pragma unroll
    for (int r = 0; r < 6; ++r) {
        bool sel = (key[r] <= thr);
        unsigned int bm = __ballot_sync(0xFFFFFFFFu, sel);
        if (sel) {
            int lane = t & 31;
            int base = 0;
            if (__ffs(bm) - 1 == lane)
                base = atomicAdd(&sh_nc, __popc(bm));
            base = __shfl_sync(bm, base, __ffs(bm) - 1);
            int pos = base + __popc(bm & ((1u << lane) - 1));
            if (pos < CSORT)
                cand[pos] = ((unsigned long long)key[r] << 32) |
                            (unsigned int)(r * 1024 + t);
        }
    }
    __syncthreads();
    const int nc = sh_nc;
    if (t >= nc) cand[t] = 0xFFFFFFFFFFFFFFFFull;
    __syncthreads();

    const unsigned long long myc = cand[t];
    const unsigned int mykey = (unsigned int)(myc >> 32);
    const int myidx = (int)(unsigned int)(myc & 0xFFFFFFFFull);

    // exact participation at the threshold key (m smallest indices)
    unsigned long long tv = (t < nc && mykey == thr)
        ? (unsigned long long)(unsigned int)myidx : 0xFFFFFFFFFFFFFFFFull;
    int idx_thr = -1;
    for (int it = 0; it < m; ++it) {
        unsigned long long mn = blockMinU64(tv, s_red, t);
        idx_thr = (int)(unsigned int)mn;
        if (tv == mn) tv = 0xFFFFFFFFFFFFFFFFull;
    }
    bool alive = (t < nc) &&
                 (mykey < thr || (mykey == thr && myidx <= idx_thr));

    // ---- greedy NMS: iterated extract-min ----
    if (t == 0) sh_kc = 0;
    while (true) {
        unsigned long long v = alive ? myc : 0xFFFFFFFFFFFFFFFFull;
        unsigned long long win = blockMinU64(v, s_red, t);
        if (win == 0xFFFFFFFFFFFFFFFFull) break;
        const int oi = (int)(unsigned int)(win & 0xFFFFFFFFull);
        if (t == 0) {
            int kp = sh_kc;
            if (kp < KCAP) {
                s_kidx[kp] = oi;
                s_klv[kp] = ((unsigned long long)(~(unsigned int)(win >> 32)) << 32) |
                            (unsigned long long)(unsigned int)(NCLS - c);
            }
            sh_kc = kp + 1;
        }
        if (alive) {
            float vio = iou[(size_t)oi * NROI + myidx];
            if (vio >= IOU_TH) alive = false;
        }
    }

    __syncthreads();
    const int kcnt = min(sh_kc, KCAP);
    if (t == 0) sh_base = atomicAdd(&g_cnt, kcnt);
    __syncthreads();
    if (t < kcnt) {
        g_list[sh_base + t] = s_kidx[t];
        g_lv[sh_base + t]   = s_klv[t];
    }
}

// ============================================================
// Kernel 2: fused partial-max + list-scan resolution
// (PDL-dependent on class_nms).
// ============================================================
__global__ void __launch_bounds__(1024, 1)
fused_final_kernel(const float* __restrict__ iou, float* __restrict__ out) {
    __shared__ int s_idx[GMAX];
    __shared__ unsigned long long s_lvl[GMAX];
    __shared__ unsigned long long s_part[1024];
    __shared__ int   s_lab[128];
    __shared__ float s_v[128];
    __shared__ float s_w[128];

    const int t  = threadIdx.x;
    const int bi = blockIdx.x;
    const int il = t & 127;
    const int ch = t >> 7;
    const int i  = bi * 128 + il;

    cudaGridDependencySynchronize();                    // class grid complete

    const int G = min(g_cnt, GMAX);

    for (int e = t; e < G; e += 1024) {
        s_idx[e] = g_list[e];
        s_lvl[e] = g_lv[e];
    }
    __syncthreads();

    const int len = (G + 7) >> 3;
    const int g0 = ch * len;
    const int g1 = min(G, g0 + len);

    unsigned long long pkey = 0ull;
    if (g0 < g1) {
        float mv[8]; int mj[8];
        #pragma unroll
        for (int r = 0; r < 8; ++r) { mv[r] = -1.0f; mj[r] = 0; }
        int g = g0;
        for (; g + 8 <= g1; g += 8) {
            #pragma unroll
            for (int r = 0; r < 8; ++r) {
                int j = s_idx[g + r];
                upd(mv[r], mj[r], iou[(size_t)j * NROI + i], j);
            }
        }
        #pragma unroll 8
        for (; g < g1; ++g) {
            int j = s_idx[g];
            upd(mv[0], mj[0], iou[(size_t)j * NROI + i], j);
        }
        #pragma unroll
        for (int r = 4; r >= 1; r >>= 1)
            #pragma unroll
            for (int r2 = 0; r2 < 8; ++r2)
                if (r2 < r) upd(mv[r2], mj[r2], mv[r2 + r], mj[r2 + r]);
        pkey = ((unsigned long long)__float_as_uint(mv[0]) << 32) |
               (unsigned long long)(unsigned int)(NROI - mj[0]);
    }
    s_part[t] = pkey;
    __syncthreads();

    if (t < 128) {
        unsigned long long best = s_part[t];
        #pragma unroll
        for (int r = 1; r < 8; ++r) {
            unsigned long long b2 = s_part[t + r * 128];
            if (b2 > best) best = b2;
        }
        const float maxv = __uint_as_float((unsigned int)(best >> 32));
        const int   maxj = NROI - (int)(unsigned int)(best & 0xFFFFFFFFull);

        unsigned long long lv = 0ull;
        for (int e = 0; e < G; ++e)
            if (s_idx[e] == maxj) {
                unsigned long long x = s_lvl[e];
                if (x > lv) lv = x;
            }
        const int   cls = (int)(NCLS + 1) - (int)(unsigned int)(lv & 0xFFFFFFFFull);
        const float lw  = __uint_as_float((unsigned int)(lv >> 32));

        const bool ignore = (maxv == 0.0f);
        const bool bg     = (maxv < IOU_TH) && !ignore;
        s_lab[t] = ignore ? -1 : (bg ? 0 : cls);
        s_v[t]   = maxv;
        s_w[t]   = ignore ? 0.0f : lw;
    }
    __syncthreads();

    const size_t base = (size_t)bi * 128 * (NCLS + 1);
    for (int e = t; e < 128 * (NCLS + 1); e += 1024) {
        int row = e / (NCLS + 1);
        int k   = e - row * (NCLS + 1);
        out[base + e] = (k == s_lab[row]) ? 1.0f : 0.0f;
    }
    if (t < 128) {
        out[(size_t)NROI * (NCLS + 1) + i]        = s_v[t];
        out[(size_t)NROI * (NCLS + 1) + NROI + i] = s_w[t];
    }

    if (bi == 0 && t == 0) g_cnt = 0;
}

extern "C" void kernel_launch(void* const* d_in, const int* in_sizes, int n_in,
                              void* d_out, int out_size) {
    const float* pc     = (const float*)d_in[0];
    const float* pd     = (const float*)d_in[1];
    // d_in[2] = rois (unused)
    const int*   labels = (const int*)d_in[3];
    const float* iou    = (const float*)d_in[4];
    float* out = (float*)d_out;

    preds_kernel<<<96, 256>>>((const float4*)pc, (const float4*)pd, labels);

    {
        cudaLaunchConfig_t cfg = {};
        cfg.gridDim  = dim3(NCLS, 1, 1);
        cfg.blockDim = dim3(1024, 1, 1);
        cudaLaunchAttribute attr[1];
        attr[0].id = cudaLaunchAttributeProgrammaticStreamSerialization;
        attr[0].val.programmaticStreamSerializationAllowed = 1;
        cfg.attrs = attr;
        cfg.numAttrs = 1;
        cudaLaunchKernelEx(&cfg, class_nms_kernel, labels, iou);
    }
    {
        cudaLaunchConfig_t cfg = {};
        cfg.gridDim  = dim3(NFB, 1, 1);
        cfg.blockDim = dim3(1024, 1, 1);
        cudaLaunchAttribute attr[1];
        attr[0].id = cudaLaunchAttributeProgrammaticStreamSerialization;
        attr[0].val.programmaticStreamSerializationAllowed = 1;
        cfg.attrs = attr;
        cfg.numAttrs = 1;
        cudaLaunchKernelEx(&cfg, fused_final_kernel, iou, out);
    }
}